// round 2
// baseline (speedup 1.0000x reference)
#include <cuda_runtime.h>

// Conv2d: x[32,64,56,56] (f32) * filters[128,64,3,3] -> out[32,128,56,56]
// stride 1, pad 1.
//
// Register-blocked direct convolution, FMA-roofline targeted:
//  - Block: one batch b, one 8x8 spatial tile, 64 output channels, 128 threads.
//  - Thread: one 8-wide pixel row x 4 output channels = 32 accumulators.
//  - Input channels staged in chunks of 16 through shared memory.
//  - Warp layout (pg=t&7, og=t>>3) gives conflict-free stride-10 input LDS
//    and broadcast weight LDS.128.
//  - Filters pre-transposed once into [c][k][oc] so staging is LDG.128/STS.128.

#define B_    32
#define CIN   64
#define HW    56
#define COUT  128
#define TH    8
#define TW    8
#define CCH   16      // cin chunk
#define OCT   64      // output channels per block
#define KK    9       // 3x3

// Transposed filter scratch: wt[(c*9+k)*COUT + oc]
__device__ float g_wt[CIN * KK * COUT];

__global__ void transpose_filters(const float* __restrict__ w) {
    int i = blockIdx.x * blockDim.x + threadIdx.x;
    if (i < CIN * KK * COUT) {
        int oc = i % COUT;
        int ck = i / COUT;               // c*9 + k
        g_wt[i] = w[(size_t)oc * (CIN * KK) + ck];
    }
}

__global__ __launch_bounds__(128) void conv3x3_kernel(
    const float* __restrict__ x,
    float* __restrict__ out)
{
    __shared__ float s_in[CCH][TH + 2][TW + 2];   // 16 x 10 x 10 = 6.4 KB
    __shared__ float s_w[CCH][KK][OCT];           // 16 x 9 x 64  = 36.9 KB

    const int t     = threadIdx.x;                // 0..127
    const int tile  = blockIdx.x;                 // 0..48  (7x7 tiles)
    const int ocg   = blockIdx.y;                 // 0..1
    const int b     = blockIdx.z;                 // 0..31

    const int ty0 = (tile / (HW / TH)) * TH;
    const int tx0 = (tile % (HW / TW)) * TW;
    const int oc0 = ocg * OCT;

    const int pr = t & 7;                         // pixel row 0..7 (full 8-wide row)
    const int og = t >> 3;                        // oc group 0..15 (4 oc each)

    float acc[4][8];                              // [oc][px]
    #pragma unroll
    for (int q = 0; q < 4; q++)
        #pragma unroll
        for (int p = 0; p < 8; p++)
            acc[q][p] = 0.f;

    const float* xb = x + (size_t)b * CIN * HW * HW;

    for (int c0 = 0; c0 < CIN; c0 += CCH) {
        // ---- stage input halo tile: CCH x 10 x 10 ----
        for (int i = t; i < CCH * (TH + 2) * (TW + 2); i += 128) {
            int cc  = i / ((TH + 2) * (TW + 2));
            int rem = i % ((TH + 2) * (TW + 2));
            int iy  = rem / (TW + 2);
            int ix  = rem % (TW + 2);
            int gy  = ty0 - 1 + iy;
            int gx  = tx0 - 1 + ix;
            float v = 0.f;
            if ((unsigned)gy < HW && (unsigned)gx < HW)
                v = xb[((size_t)(c0 + cc) * HW + gy) * HW + gx];
            s_in[cc][iy][ix] = v;
        }
        // ---- stage weights vectorized: 2304 float4, conflict-free ----
        {
            float4* s_w4 = reinterpret_cast<float4*>(&s_w[0][0][0]);
            for (int i = t; i < CCH * KK * OCT / 4; i += 128) {
                int oc4 = i & 15;                 // 16 float4 per (cc,k) row
                int ck  = i >> 4;                 // cc*9 + k
                int cc  = ck / KK;
                int k   = ck % KK;
                const float4* src = reinterpret_cast<const float4*>(
                    &g_wt[((size_t)(c0 + cc) * KK + k) * COUT + oc0 + oc4 * 4]);
                s_w4[i] = *src;
            }
        }
        __syncthreads();

        // ---- compute ----
        for (int cc = 0; cc < CCH; cc++) {
            // window: 3 rows x 10 cols of input (covers 8 output px + halo)
            float a0[3][10];
            #pragma unroll
            for (int r = 0; r < 3; r++)
                #pragma unroll
                for (int j = 0; j < 10; j++)
                    a0[r][j] = s_in[cc][pr + r][j];

            #pragma unroll
            for (int kh = 0; kh < 3; kh++) {
                #pragma unroll
                for (int kw = 0; kw < 3; kw++) {
                    float4 wv = *reinterpret_cast<const float4*>(
                        &s_w[cc][kh * 3 + kw][og * 4]);
                    #pragma unroll
                    for (int p = 0; p < 8; p++) {
                        float xv = a0[kh][kw + p];
                        acc[0][p] += xv * wv.x;
                        acc[1][p] += xv * wv.y;
                        acc[2][p] += xv * wv.z;
                        acc[3][p] += xv * wv.w;
                    }
                }
            }
        }
        __syncthreads();
    }

    // ---- store: 4 oc rows x 8 consecutive px each (2x STG.128 per oc) ----
    const int oy = ty0 + pr;
    #pragma unroll
    for (int q = 0; q < 4; q++) {
        int oc = oc0 + og * 4 + q;
        float* dst = &out[(((size_t)b * COUT + oc) * HW + oy) * HW + tx0];
        *reinterpret_cast<float4*>(dst) =
            make_float4(acc[q][0], acc[q][1], acc[q][2], acc[q][3]);
        *reinterpret_cast<float4*>(dst + 4) =
            make_float4(acc[q][4], acc[q][5], acc[q][6], acc[q][7]);
    }
}

extern "C" void kernel_launch(void* const* d_in, const int* in_sizes, int n_in,
                              void* d_out, int out_size) {
    const float* x = (const float*)d_in[0];
    const float* w = (const float*)d_in[1];
    float* out = (float*)d_out;

    int nwt = CIN * KK * COUT;
    transpose_filters<<<(nwt + 255) / 256, 256>>>(w);

    dim3 grid((HW / TH) * (HW / TW), COUT / OCT, B_);  // 49 x 2 x 32
    conv3x3_kernel<<<grid, 128>>>(x, out);
}

// round 4
// speedup vs baseline: 2.5783x; 2.5783x over previous
#include <cuda_runtime.h>
#include <cstdint>

// Conv2d 3x3 s1 p1: x[32,64,56,56] * w[128,64,3,3] -> out[32,128,56,56]
// TF32 implicit GEMM on legacy mma.sync (m16n8k8) tensor path (sm_100 base target).
// M=128(oc), N=100352(px), K=576=(kh,kw,c).

#define B_    32
#define CIN   64
#define COUT  128
#define HW    56
#define PADW  58
#define IMG   (HW*HW)             // 3136
#define NPIX  (B_*IMG)            // 100352
#define NT    128                 // pixels per CTA
#define NCTA  (NPIX/NT)           // 784
#define BSTR  68                  // padded B smem stride (floats)

// Scratch: zero-padded NHWC input (tf32-rounded), fragment-major weights
__device__ float g_xpad[(size_t)B_*PADW*PADW*CIN];   // 27.5 MB
__device__ float g_wt2[9*COUT*CIN];                  // [k][s][atom][lane][4]

static __device__ __forceinline__ float to_tf32(float v) {
    uint32_t o; asm("cvt.rna.tf32.f32 %0, %1;" : "=r"(o) : "f"(v));
    return __uint_as_float(o);
}

static __device__ __forceinline__ void mma8(float* d, const uint32_t* a,
                                            uint32_t b0, uint32_t b1) {
    asm volatile("mma.sync.aligned.m16n8k8.row.col.f32.tf32.tf32.f32 "
                 "{%0,%1,%2,%3}, {%4,%5,%6,%7}, {%8,%9}, {%0,%1,%2,%3};"
                 : "+f"(d[0]), "+f"(d[1]), "+f"(d[2]), "+f"(d[3])
                 : "r"(a[0]), "r"(a[1]), "r"(a[2]), "r"(a[3]),
                   "r"(b0), "r"(b1));
}

// ---------------- prep kernels ----------------
// NCHW -> padded NHWC (tf32-rounded) via smem transpose. grid (56, 32), 256 thr.
__global__ void k_transpose(const float* __restrict__ x) {
    __shared__ float s[CIN][HW + 1];
    int y = blockIdx.x, b = blockIdx.y, t = threadIdx.x;
    for (int i = t; i < CIN * HW; i += 256) {
        int c = i / HW, xx = i % HW;
        s[c][xx] = to_tf32(x[(((size_t)b * CIN + c) * HW + y) * HW + xx]);
    }
    __syncthreads();
    float* dst = g_xpad + (((size_t)b * PADW + (y + 1)) * PADW + 1) * CIN;
    for (int i = t; i < HW * CIN; i += 256) {
        int px = i / CIN, c = i % CIN;
        dst[(size_t)px * CIN + c] = s[c][px];
    }
}

// zero the padded borders of g_xpad
__global__ void k_border() {
    int i = blockIdx.x * blockDim.x + threadIdx.x;
    const int per_b = 228 * CIN;
    if (i >= B_ * per_b) return;
    int b = i / per_b, r = i % per_b;
    int cell = r / CIN, c = r % CIN;
    int yy, xx;
    if (cell < 58)       { yy = 0;  xx = cell; }
    else if (cell < 116) { yy = 57; xx = cell - 58; }
    else if (cell < 172) { yy = cell - 116 + 1; xx = 0; }
    else                 { yy = cell - 172 + 1; xx = 57; }
    g_xpad[(((size_t)b * PADW + yy) * PADW + xx) * CIN + c] = 0.f;
}

// W[oc][c][3][3] -> A-fragment-major per k-chunk:
// g_wt2[k][s(8)][atom(8)][lane(32)][j(4)],
// oc = atom*16 + lane/4 + (j&1)*8,  c = s*8 + lane%4 + (j>>1)*4
__global__ void k_wt(const float* __restrict__ w) {
    int i = blockIdx.x * blockDim.x + threadIdx.x;
    if (i >= 9 * COUT * CIN) return;
    int k    = i / 8192;
    int e    = i % 8192;
    int s    = e / 1024;
    int atom = (e / 128) & 7;
    int lane = (e >> 2) & 31;
    int j    = e & 3;
    int oc = atom * 16 + (lane >> 2) + (j & 1) * 8;
    int c  = s * 8 + (lane & 3) + (j >> 1) * 4;
    g_wt2[i] = to_tf32(w[((size_t)oc * CIN + c) * 9 + k]);
}

// ---------------- main kernel ----------------
// smem: [0]=s_pix(128 u32) [512]=s_out4(32 u32) [1024]=A(32768)+B(34816)
//       epilogue reuses [1024] as sO (128 x 132 floats = 67584)
#define SM_A    1024
#define SM_B    (SM_A + 32768)
#define SM_TOT  (SM_B + NT*BSTR*4)     // 1024+32768+34816 = 68608

__global__ __launch_bounds__(256, 2) void conv_mma(float* __restrict__ out) {
    extern __shared__ char smem[];
    uint32_t* s_pix  = (uint32_t*)smem;
    uint32_t* s_out4 = (uint32_t*)(smem + 512);
    float* sA = (float*)(smem + SM_A);
    float* sB = (float*)(smem + SM_B);
    float* sO = (float*)(smem + SM_A);

    const int t = threadIdx.x;
    const int w = t >> 5, lane = t & 31;
    const int g = lane >> 2, tig = lane & 3;
    const int ocHalf = w & 1, pxQ = w >> 1;
    const int base = blockIdx.x * NT;

    if (t < NT) {
        int ng = base + t;
        int bb = ng / IMG, rr = ng - bb * IMG;
        int y = rr / HW, xx = rr - y * HW;
        s_pix[t] = (((uint32_t)bb * PADW + y) * PADW + xx) * CIN;
    }
    if (t < NT / 4) {
        int ng = base + t * 4;
        int bb = ng / IMG, rr = ng - bb * IMG;
        s_out4[t] = (uint32_t)bb * COUT * IMG + rr;
    }
    __syncthreads();

    float d[4][4][4];
    #pragma unroll
    for (int ao = 0; ao < 4; ao++)
        #pragma unroll
        for (int an = 0; an < 4; an++)
            #pragma unroll
            for (int j = 0; j < 4; j++) d[ao][an][j] = 0.f;

    const float* aBase = sA + (ocHalf * 4) * 128 + lane * 4;
    const float* bBase = sB + (pxQ * 32 + g) * BSTR + tig;

    for (int k = 0; k < 9; k++) {
        // stage A: contiguous fragment-major copy, 2048 float4
        {
            const float4* src = (const float4*)(g_wt2 + k * 8192);
            float4* dst = (float4*)sA;
            #pragma unroll
            for (int it = 0; it < 8; it++)
                dst[t + it * 256] = src[t + it * 256];
        }
        // stage B: 128 px x 64 c, padded stride 68
        {
            const uint32_t shift = (uint32_t)((k / 3) * PADW + (k % 3)) * CIN;
            #pragma unroll
            for (int it = 0; it < 8; it++) {
                int i = t + it * 256;
                int px = i >> 4, c4 = i & 15;
                float4 v = *(const float4*)(g_xpad + s_pix[px] + shift + c4 * 4);
                *(float4*)(sB + px * BSTR + c4 * 4) = v;
            }
        }
        __syncthreads();

        #pragma unroll
        for (int s = 0; s < 8; s++) {
            uint32_t a[4][4];
            #pragma unroll
            for (int ao = 0; ao < 4; ao++) {
                uint4 v = *(const uint4*)(aBase + s * 1024 + ao * 128);
                a[ao][0] = v.x; a[ao][1] = v.y; a[ao][2] = v.z; a[ao][3] = v.w;
            }
            uint32_t b0[4], b1[4];
            #pragma unroll
            for (int an = 0; an < 4; an++) {
                b0[an] = __float_as_uint(bBase[an * 8 * BSTR + s * 8]);
                b1[an] = __float_as_uint(bBase[an * 8 * BSTR + s * 8 + 4]);
            }
            #pragma unroll
            for (int ao = 0; ao < 4; ao++)
                #pragma unroll
                for (int an = 0; an < 4; an++)
                    mma8(d[ao][an], a[ao], b0[an], b1[an]);
        }
        __syncthreads();
    }

    // epilogue: accums -> sO[oc][132] -> coalesced STG.128
    #pragma unroll
    for (int ao = 0; ao < 4; ao++)
        #pragma unroll
        for (int an = 0; an < 4; an++)
            #pragma unroll
            for (int j = 0; j < 4; j++) {
                int oc = ocHalf * 64 + ao * 16 + g + ((j >> 1) << 3);
                int px = pxQ * 32 + an * 8 + 2 * tig + (j & 1);
                sO[oc * 132 + px] = d[ao][an][j];
            }
    __syncthreads();

    #pragma unroll
    for (int it = 0; it < 16; it++) {
        int i = t + it * 256;
        int oc = i >> 5, q = lane;
        float4 v = *(const float4*)(sO + oc * 132 + q * 4);
        *(float4*)(out + (size_t)s_out4[q] + (size_t)oc * IMG) = v;
    }
}

extern "C" void kernel_launch(void* const* d_in, const int* in_sizes, int n_in,
                              void* d_out, int out_size) {
    const float* x = (const float*)d_in[0];
    const float* w = (const float*)d_in[1];
    float* out = (float*)d_out;

    k_border<<<(B_ * 228 * CIN + 255) / 256, 256>>>();
    k_wt<<<(9 * COUT * CIN + 255) / 256, 256>>>(w);
    k_transpose<<<dim3(HW, B_), 256>>>(x);

    cudaFuncSetAttribute(conv_mma, cudaFuncAttributeMaxDynamicSharedMemorySize, SM_TOT);
    conv_mma<<<NCTA, 256, SM_TOT>>>(out);
}

// round 5
// speedup vs baseline: 2.9179x; 1.1317x over previous
#include <cuda_runtime.h>
#include <cstdint>

// Conv2d 3x3 s1 p1: x[32,64,56,56] * w[128,64,3,3] -> out[32,128,56,56]
// TF32 implicit GEMM on mma.sync m16n8k8 (sm_100 base target), now with
// cp.async double-buffered k-chunk pipeline. M=128(oc), N=100352(px), K=576.

#define B_    32
#define CIN   64
#define COUT  128
#define HW    56
#define PADW  58
#define IMG   (HW*HW)             // 3136
#define NPIX  (B_*IMG)            // 100352
#define NT    256                 // pixels per CTA
#define NCTA  (NPIX/NT)           // 392
#define BSTR  68                  // padded B smem stride (floats)
#define NTHR  512

__device__ float g_xpad[(size_t)B_*PADW*PADW*CIN];   // 27.5 MB, tf32-rounded NHWC
__device__ float g_wt2[9*COUT*CIN];                  // fragment-major weights

static __device__ __forceinline__ float to_tf32(float v) {
    uint32_t o; asm("cvt.rna.tf32.f32 %0, %1;" : "=r"(o) : "f"(v));
    return __uint_as_float(o);
}
static __device__ __forceinline__ void mma8(float* d, const uint32_t* a,
                                            uint32_t b0, uint32_t b1) {
    asm volatile("mma.sync.aligned.m16n8k8.row.col.f32.tf32.tf32.f32 "
                 "{%0,%1,%2,%3}, {%4,%5,%6,%7}, {%8,%9}, {%0,%1,%2,%3};"
                 : "+f"(d[0]), "+f"(d[1]), "+f"(d[2]), "+f"(d[3])
                 : "r"(a[0]), "r"(a[1]), "r"(a[2]), "r"(a[3]), "r"(b0), "r"(b1));
}
static __device__ __forceinline__ void cp16(uint32_t saddr, const void* g) {
    asm volatile("cp.async.cg.shared.global [%0], [%1], 16;" :: "r"(saddr), "l"(g));
}
#define CP_COMMIT() asm volatile("cp.async.commit_group;" ::: "memory")
#define CP_WAIT(n)  asm volatile("cp.async.wait_group %0;" :: "n"(n) : "memory")

// ---------------- prep kernels ----------------
__global__ void k_transpose(const float* __restrict__ x) {
    __shared__ float s[CIN][HW + 1];
    int y = blockIdx.x, b = blockIdx.y, t = threadIdx.x;
    for (int i = t; i < CIN * HW; i += 256) {
        int c = i / HW, xx = i % HW;
        s[c][xx] = to_tf32(x[(((size_t)b * CIN + c) * HW + y) * HW + xx]);
    }
    __syncthreads();
    float* dst = g_xpad + (((size_t)b * PADW + (y + 1)) * PADW + 1) * CIN;
    for (int i = t; i < HW * CIN; i += 256) {
        int px = i / CIN, c = i % CIN;
        dst[(size_t)px * CIN + c] = s[c][px];
    }
}
__global__ void k_border() {
    int i = blockIdx.x * blockDim.x + threadIdx.x;
    const int per_b = 228 * CIN;
    if (i >= B_ * per_b) return;
    int b = i / per_b, r = i % per_b;
    int cell = r / CIN, c = r % CIN;
    int yy, xx;
    if (cell < 58)       { yy = 0;  xx = cell; }
    else if (cell < 116) { yy = 57; xx = cell - 58; }
    else if (cell < 172) { yy = cell - 116 + 1; xx = 0; }
    else                 { yy = cell - 172 + 1; xx = 57; }
    g_xpad[(((size_t)b * PADW + yy) * PADW + xx) * CIN + c] = 0.f;
}
// W[oc][c][3][3] -> g_wt2[k][s(8)][atom(8)][lane(32)][j(4)]
__global__ void k_wt(const float* __restrict__ w) {
    int i = blockIdx.x * blockDim.x + threadIdx.x;
    if (i >= 9 * COUT * CIN) return;
    int k    = i / 8192;
    int e    = i % 8192;
    int s    = e / 1024;
    int atom = (e / 128) & 7;
    int lane = (e >> 2) & 31;
    int j    = e & 3;
    int oc = atom * 16 + (lane >> 2) + (j & 1) * 8;
    int c  = s * 8 + (lane & 3) + (j >> 1) * 4;
    g_wt2[i] = to_tf32(w[((size_t)oc * CIN + c) * 9 + k]);
}

// ---------------- main kernel ----------------
// smem bytes: [0]=s_pix(256 u32) [1024]=s_out4(64 u32) [2048]=A0(32K)
//             [34816]=A1(32K) [67584]=B0(69632) [137216]=B1(69632)  tot 206848
// epilogue reuses [2048..] as sO[128][260] floats (133120 B)
#define SM_A0   2048
#define SM_A1   (SM_A0 + 32768)
#define SM_B0   (SM_A1 + 32768)
#define SM_B1   (SM_B0 + NT*BSTR*4)
#define SM_TOT  (SM_B1 + NT*BSTR*4)

__global__ __launch_bounds__(NTHR, 1) void conv_mma(float* __restrict__ out) {
    extern __shared__ char smem[];
    uint32_t* s_pix  = (uint32_t*)smem;
    uint32_t* s_out4 = (uint32_t*)(smem + 1024);
    const uint32_t sb = (uint32_t)__cvta_generic_to_shared(smem);

    const int t = threadIdx.x;
    const int w = t >> 5, lane = t & 31;
    const int g = lane >> 2, tig = lane & 3;
    const int ocHalf = w & 1, pxQ = w >> 1;          // 2 x 8 warp grid
    const int base = blockIdx.x * NT;

    if (t < NT) {
        int ng = base + t;
        int bb = ng / IMG, rr = ng - bb * IMG;
        int y = rr / HW, xx = rr - y * HW;
        s_pix[t] = (((uint32_t)bb * PADW + y) * PADW + xx) * CIN;
    }
    if (t < NT / 4) {
        int ng = base + t * 4;
        int bb = ng / IMG, rr = ng - bb * IMG;
        s_out4[t] = (uint32_t)bb * COUT * IMG + rr;
    }
    __syncthreads();

    float d[4][4][4];
    #pragma unroll
    for (int ao = 0; ao < 4; ao++)
        #pragma unroll
        for (int an = 0; an < 4; an++)
            #pragma unroll
            for (int j = 0; j < 4; j++) d[ao][an][j] = 0.f;

    // staging lambda-ish: stage chunk k into buffer buf
    auto stage = [&](int k, int buf) {
        const uint32_t abuf = sb + (buf ? SM_A1 : SM_A0);
        const uint32_t bbuf = sb + (buf ? SM_B1 : SM_B0);
        const float* asrc = g_wt2 + k * 8192;
        #pragma unroll
        for (int it = 0; it < 4; it++) {
            int i = t + it * NTHR;                       // float4 index
            cp16(abuf + i * 16, asrc + i * 4);
        }
        const uint32_t shift = (uint32_t)((k / 3) * PADW + (k % 3)) * CIN;
        #pragma unroll
        for (int it = 0; it < 8; it++) {
            int i = t + it * NTHR;
            int px = i >> 4, c4 = i & 15;
            cp16(bbuf + (px * BSTR + c4 * 4) * 4,
                 g_xpad + s_pix[px] + shift + c4 * 4);
        }
    };

    stage(0, 0); CP_COMMIT();

    for (int k = 0; k < 9; k++) {
        if (k < 8) { stage(k + 1, (k + 1) & 1); CP_COMMIT(); CP_WAIT(1); }
        else       { CP_WAIT(0); }
        __syncthreads();

        const float* sA = (const float*)(smem + ((k & 1) ? SM_A1 : SM_A0));
        const float* sB = (const float*)(smem + ((k & 1) ? SM_B1 : SM_B0));
        const float* aBase = sA + (ocHalf * 4) * 128 + lane * 4;
        const float* bBase = sB + (pxQ * 32 + g) * BSTR + tig;

        #pragma unroll
        for (int s = 0; s < 8; s++) {
            uint32_t a[4][4];
            #pragma unroll
            for (int ao = 0; ao < 4; ao++) {
                uint4 v = *(const uint4*)(aBase + s * 1024 + ao * 128);
                a[ao][0] = v.x; a[ao][1] = v.y; a[ao][2] = v.z; a[ao][3] = v.w;
            }
            uint32_t b0[4], b1[4];
            #pragma unroll
            for (int an = 0; an < 4; an++) {
                b0[an] = __float_as_uint(bBase[an * 8 * BSTR + s * 8]);
                b1[an] = __float_as_uint(bBase[an * 8 * BSTR + s * 8 + 4]);
            }
            #pragma unroll
            for (int ao = 0; ao < 4; ao++)
                #pragma unroll
                for (int an = 0; an < 4; an++)
                    mma8(d[ao][an], a[ao], b0[an], b1[an]);
        }
        __syncthreads();
    }

    // epilogue: accums -> sO[oc][260] -> coalesced STG.128
    float* sO = (float*)(smem + SM_A0);
    #pragma unroll
    for (int ao = 0; ao < 4; ao++)
        #pragma unroll
        for (int an = 0; an < 4; an++)
            #pragma unroll
            for (int j = 0; j < 4; j++) {
                int oc = ocHalf * 64 + ao * 16 + g + ((j >> 1) << 3);
                int px = pxQ * 32 + an * 8 + 2 * tig + (j & 1);
                sO[oc * 260 + px] = d[ao][an][j];
            }
    __syncthreads();

    #pragma unroll
    for (int it = 0; it < 16; it++) {
        int i = t + it * NTHR;
        int oc = i >> 6, q = i & 63;                     // 64 float4 per oc row
        float4 v = *(const float4*)(sO + oc * 260 + q * 4);
        *(float4*)(out + (size_t)s_out4[q] + (size_t)oc * IMG) = v;
    }
}

extern "C" void kernel_launch(void* const* d_in, const int* in_sizes, int n_in,
                              void* d_out, int out_size) {
    const float* x = (const float*)d_in[0];
    const float* w = (const float*)d_in[1];
    float* out = (float*)d_out;

    k_border<<<(B_ * 228 * CIN + 255) / 256, 256>>>();
    k_wt<<<(9 * COUT * CIN + 255) / 256, 256>>>(w);
    k_transpose<<<dim3(HW, B_), 256>>>(x);

    cudaFuncSetAttribute(conv_mma, cudaFuncAttributeMaxDynamicSharedMemorySize, SM_TOT);
    conv_mma<<<NCTA, NTHR, SM_TOT>>>(out);
}

// round 6
// speedup vs baseline: 3.1225x; 1.0701x over previous
#include <cuda_runtime.h>
#include <cstdint>

// Conv2d 3x3 s1 p1: x[32,64,56,56] * w[128,64,3,3] -> out[32,128,56,56]
// TF32 implicit GEMM, mma.sync m16n8k8. cp.async double-buffered 32-channel
// k-chunks (18 steps), 2 CTAs/SM for cross-CTA latency hiding.

#define B_    32
#define CIN   64
#define COUT  128
#define HW    56
#define PADW  58
#define IMG   (HW*HW)             // 3136
#define NPIX  (B_*IMG)            // 100352
#define NT    128                 // pixels per CTA
#define NCTA  (NPIX/NT)           // 784
#define BSTR  36                  // padded B smem stride (floats), 32ch chunk
#define NTHR  256

__device__ float g_xpad[(size_t)B_*PADW*PADW*CIN];   // 27.5 MB, tf32-rounded NHWC
__device__ float g_wt2[9*COUT*CIN];                  // fragment-major weights

static __device__ __forceinline__ float to_tf32(float v) {
    uint32_t o; asm("cvt.rna.tf32.f32 %0, %1;" : "=r"(o) : "f"(v));
    return __uint_as_float(o);
}
static __device__ __forceinline__ void mma8(float* d, const uint32_t* a,
                                            uint32_t b0, uint32_t b1) {
    asm volatile("mma.sync.aligned.m16n8k8.row.col.f32.tf32.tf32.f32 "
                 "{%0,%1,%2,%3}, {%4,%5,%6,%7}, {%8,%9}, {%0,%1,%2,%3};"
                 : "+f"(d[0]), "+f"(d[1]), "+f"(d[2]), "+f"(d[3])
                 : "r"(a[0]), "r"(a[1]), "r"(a[2]), "r"(a[3]), "r"(b0), "r"(b1));
}
static __device__ __forceinline__ void cp16(uint32_t saddr, const void* g) {
    asm volatile("cp.async.cg.shared.global [%0], [%1], 16;" :: "r"(saddr), "l"(g));
}
#define CP_COMMIT() asm volatile("cp.async.commit_group;" ::: "memory")
#define CP_WAIT(n)  asm volatile("cp.async.wait_group %0;" :: "n"(n) : "memory")

// ---------------- prep kernels ----------------
// NCHW -> padded NHWC (tf32-rounded), border zeroing fused. grid (58, 32).
__global__ void k_transpose(const float* __restrict__ x) {
    int yp = blockIdx.x, b = blockIdx.y, t = threadIdx.x;
    float* dst = g_xpad + ((size_t)b * PADW + yp) * PADW * CIN;
    if (yp == 0 || yp == PADW - 1) {
        for (int i = t; i < PADW * CIN; i += NTHR) dst[i] = 0.f;
        return;
    }
    __shared__ float s[CIN][HW + 1];
    int y = yp - 1;
    for (int i = t; i < CIN * HW; i += NTHR) {
        int c = i / HW, xx = i % HW;
        s[c][xx] = to_tf32(x[(((size_t)b * CIN + c) * HW + y) * HW + xx]);
    }
    __syncthreads();
    if (t < 2 * CIN) {               // zero left/right halo columns
        int side = t >> 6, c = t & 63;
        dst[(side ? (PADW - 1) * CIN : 0) + c] = 0.f;
    }
    for (int i = t; i < HW * CIN; i += NTHR) {
        int px = i / CIN, c = i % CIN;
        dst[(px + 1) * CIN + c] = s[c][px];
    }
}
// W[oc][c][3][3] -> g_wt2[k][s(8)][atom(8)][lane(32)][j(4)]
__global__ void k_wt(const float* __restrict__ w) {
    int i = blockIdx.x * blockDim.x + threadIdx.x;
    if (i >= 9 * COUT * CIN) return;
    int k    = i / 8192;
    int e    = i % 8192;
    int s    = e / 1024;
    int atom = (e / 128) & 7;
    int lane = (e >> 2) & 31;
    int j    = e & 3;
    int oc = atom * 16 + (lane >> 2) + (j & 1) * 8;
    int c  = s * 8 + (lane & 3) + (j >> 1) * 4;
    g_wt2[i] = to_tf32(w[((size_t)oc * CIN + c) * 9 + k]);
}

// ---------------- main kernel ----------------
// smem/CTA: [0] s_pix(128 u32) [512] s_out4(32 u32)
//           [1024] A0(16K) [17408] A1(16K) [33792] B0(18432) [52224] B1(18432)
//           total 70656 -> 2 CTAs/SM. Epilogue reuses [1024..] as sO[128][132].
#define SM_A0   1024
#define SM_A1   (SM_A0 + 16384)
#define SM_B0   (SM_A1 + 16384)
#define SM_B1   (SM_B0 + NT*BSTR*4)
#define SM_TOT  (SM_B1 + NT*BSTR*4)

__global__ __launch_bounds__(NTHR, 2) void conv_mma(float* __restrict__ out) {
    extern __shared__ char smem[];
    uint32_t* s_pix  = (uint32_t*)smem;
    uint32_t* s_out4 = (uint32_t*)(smem + 512);
    const uint32_t sb = (uint32_t)__cvta_generic_to_shared(smem);

    const int t = threadIdx.x;
    const int w = t >> 5, lane = t & 31;
    const int g = lane >> 2, tig = lane & 3;
    const int ocHalf = w & 1, pxQ = w >> 1;          // 2 x 4 warp grid
    const int base = blockIdx.x * NT;

    if (t < NT) {
        int ng = base + t;
        int bb = ng / IMG, rr = ng - bb * IMG;
        int y = rr / HW, xx = rr - y * HW;
        s_pix[t] = (((uint32_t)bb * PADW + y) * PADW + xx) * CIN;
    }
    if (t < NT / 4) {
        int ng = base + t * 4;
        int bb = ng / IMG, rr = ng - bb * IMG;
        s_out4[t] = (uint32_t)bb * COUT * IMG + rr;
    }
    __syncthreads();

    float d[4][4][4];
    #pragma unroll
    for (int ao = 0; ao < 4; ao++)
        #pragma unroll
        for (int an = 0; an < 4; an++)
            #pragma unroll
            for (int j = 0; j < 4; j++) d[ao][an][j] = 0.f;

    // stage 32-channel chunk kk into buffer buf
    auto stage = [&](int kk, int buf) {
        const uint32_t abuf = sb + (buf ? SM_A1 : SM_A0);
        const uint32_t bbuf = sb + (buf ? SM_B1 : SM_B0);
        const int k = kk >> 1, half = kk & 1;
        const float* asrc = g_wt2 + k * 8192 + half * 4096;
        #pragma unroll
        for (int it = 0; it < 4; it++) {
            int i = t + it * NTHR;                       // 1024 float4
            cp16(abuf + i * 16, asrc + i * 4);
        }
        const uint32_t shift = (uint32_t)((k / 3) * PADW + (k % 3)) * CIN + half * 32;
        #pragma unroll
        for (int it = 0; it < 4; it++) {
            int i = t + it * NTHR;                       // 1024 float4
            int px = i >> 3, c4 = i & 7;
            cp16(bbuf + (px * BSTR + c4 * 4) * 4,
                 g_xpad + s_pix[px] + shift + c4 * 4);
        }
    };

    stage(0, 0); CP_COMMIT();

    for (int kk = 0; kk < 18; kk++) {
        if (kk < 17) { stage(kk + 1, (kk + 1) & 1); CP_COMMIT(); CP_WAIT(1); }
        else         { CP_WAIT(0); }
        __syncthreads();

        const float* sA = (const float*)(smem + ((kk & 1) ? SM_A1 : SM_A0));
        const float* sB = (const float*)(smem + ((kk & 1) ? SM_B1 : SM_B0));
        const float* aBase = sA + ocHalf * 512 + lane * 4;
        const float* bBase = sB + (pxQ * 32 + g) * BSTR + tig;

        #pragma unroll
        for (int s = 0; s < 4; s++) {
            uint32_t a[4][4];
            #pragma unroll
            for (int ao = 0; ao < 4; ao++) {
                uint4 v = *(const uint4*)(aBase + s * 1024 + ao * 128);
                a[ao][0] = v.x; a[ao][1] = v.y; a[ao][2] = v.z; a[ao][3] = v.w;
            }
            uint32_t b0[4], b1[4];
            #pragma unroll
            for (int an = 0; an < 4; an++) {
                b0[an] = __float_as_uint(bBase[an * 8 * BSTR + s * 8]);
                b1[an] = __float_as_uint(bBase[an * 8 * BSTR + s * 8 + 4]);
            }
            #pragma unroll
            for (int ao = 0; ao < 4; ao++)
                #pragma unroll
                for (int an = 0; an < 4; an++)
                    mma8(d[ao][an], a[ao], b0[an], b1[an]);
        }
        __syncthreads();
    }

    // epilogue: accums -> sO[oc][132] -> coalesced STG.128
    float* sO = (float*)(smem + SM_A0);
    #pragma unroll
    for (int ao = 0; ao < 4; ao++)
        #pragma unroll
        for (int an = 0; an < 4; an++)
            #pragma unroll
            for (int j = 0; j < 4; j++) {
                int oc = ocHalf * 64 + ao * 16 + g + ((j >> 1) << 3);
                int px = pxQ * 32 + an * 8 + 2 * tig + (j & 1);
                sO[oc * 132 + px] = d[ao][an][j];
            }
    __syncthreads();

    #pragma unroll
    for (int it = 0; it < 16; it++) {
        int i = t + it * NTHR;                           // 4096 float4
        int oc = i >> 5, q = i & 31;
        float4 v = *(const float4*)(sO + oc * 132 + q * 4);
        *(float4*)(out + (size_t)s_out4[q] + (size_t)oc * IMG) = v;
    }
}

extern "C" void kernel_launch(void* const* d_in, const int* in_sizes, int n_in,
                              void* d_out, int out_size) {
    const float* x = (const float*)d_in[0];
    const float* w = (const float*)d_in[1];
    float* out = (float*)d_out;

    k_wt<<<(9 * COUT * CIN + 255) / 256, 256>>>(w);
    k_transpose<<<dim3(PADW, B_), NTHR>>>(x);

    cudaFuncSetAttribute(conv_mma, cudaFuncAttributeMaxDynamicSharedMemorySize, SM_TOT);
    conv_mma<<<NCTA, NTHR, SM_TOT>>>(out);
}

// round 8
// speedup vs baseline: 3.2209x; 1.0315x over previous
#include <cuda_runtime.h>
#include <cstdint>

// Conv2d 3x3 s1 p1: x[32,64,56,56] * w[128,64,3,3] -> out[32,128,56,56]
// TF32 implicit GEMM, mma.sync m16n8k8. cp.async TRIPLE-buffered 32-channel
// k-chunks (18 steps, ONE barrier per step), 2 CTAs/SM.

#define B_    32
#define CIN   64
#define COUT  128
#define HW    56
#define PADW  58
#define IMG   (HW*HW)             // 3136
#define NPIX  (B_*IMG)            // 100352
#define NT    128                 // pixels per CTA
#define NCTA  (NPIX/NT)           // 784
#define BSTR  36                  // padded B smem stride (floats), 32ch chunk
#define NTHR  256
#define TGRID (PADW*B_)           // 1856 transpose blocks

__device__ float g_xpad[(size_t)B_*PADW*PADW*CIN];   // 27.5 MB, tf32-rounded NHWC
__device__ float g_wt2[9*COUT*CIN];                  // fragment-major weights

static __device__ __forceinline__ float to_tf32(float v) {
    uint32_t o; asm("cvt.rna.tf32.f32 %0, %1;" : "=r"(o) : "f"(v));
    return __uint_as_float(o);
}
static __device__ __forceinline__ void mma8(float* d, const uint32_t* a,
                                            uint32_t b0, uint32_t b1) {
    asm volatile("mma.sync.aligned.m16n8k8.row.col.f32.tf32.tf32.f32 "
                 "{%0,%1,%2,%3}, {%4,%5,%6,%7}, {%8,%9}, {%0,%1,%2,%3};"
                 : "+f"(d[0]), "+f"(d[1]), "+f"(d[2]), "+f"(d[3])
                 : "r"(a[0]), "r"(a[1]), "r"(a[2]), "r"(a[3]), "r"(b0), "r"(b1));
}
static __device__ __forceinline__ void cp16(uint32_t saddr, const void* g) {
    asm volatile("cp.async.cg.shared.global [%0], [%1], 16;" :: "r"(saddr), "l"(g));
}
#define CP_COMMIT() asm volatile("cp.async.commit_group;" ::: "memory")
#define CP_WAIT(n)  asm volatile("cp.async.wait_group %0;" :: "n"(n) : "memory")

// ---------------- fused prep kernel ----------------
// blocks [0,1856): NCHW -> padded NHWC (tf32) with border zeroing.
// blocks [1856,2144): weight reorder to fragment-major.
__global__ void k_prep(const float* __restrict__ x, const float* __restrict__ w) {
    const int bid = blockIdx.x, t = threadIdx.x;
    if (bid < TGRID) {
        int yp = bid % PADW, b = bid / PADW;
        float* dst = g_xpad + ((size_t)b * PADW + yp) * PADW * CIN;
        if (yp == 0 || yp == PADW - 1) {
            for (int i = t; i < PADW * CIN; i += NTHR) dst[i] = 0.f;
            return;
        }
        __shared__ float s[CIN][HW + 1];
        int y = yp - 1;
        for (int i = t; i < CIN * HW; i += NTHR) {
            int c = i / HW, xx = i % HW;
            s[c][xx] = to_tf32(x[(((size_t)b * CIN + c) * HW + y) * HW + xx]);
        }
        __syncthreads();
        if (t < 2 * CIN) {               // zero left/right halo columns
            int side = t >> 6, c = t & 63;
            dst[(side ? (PADW - 1) * CIN : 0) + c] = 0.f;
        }
        for (int i = t; i < HW * CIN; i += NTHR) {
            int px = i / CIN, c = i % CIN;
            dst[(px + 1) * CIN + c] = s[c][px];
        }
    } else {
        // W[oc][c][3][3] -> g_wt2[k][s(8)][atom(8)][lane(32)][j(4)]
        int i = (bid - TGRID) * NTHR + t;
        if (i >= 9 * COUT * CIN) return;
        int k    = i / 8192;
        int e    = i % 8192;
        int s    = e / 1024;
        int atom = (e / 128) & 7;
        int lane = (e >> 2) & 31;
        int j    = e & 3;
        int oc = atom * 16 + (lane >> 2) + (j & 1) * 8;
        int c  = s * 8 + (lane & 3) + (j >> 1) * 4;
        g_wt2[i] = to_tf32(w[((size_t)oc * CIN + c) * 9 + k]);
    }
}

// ---------------- main kernel ----------------
// smem/CTA: [0] s_pix(128 u32) [512] s_out4(32 u32)
//   [1024] A0,A1,A2 (16384 each) [50176] B0,B1,B2 (18432 each)  tot 105472
//   -> 2 CTAs/SM (206 KB). Epilogue reuses [1024..] as sO[128][132] (67584 B).
#define SM_A0   1024
#define SM_B0   (SM_A0 + 3*16384)
#define SM_TOT  (SM_B0 + 3*NT*BSTR*4)

__global__ __launch_bounds__(NTHR, 2) void conv_mma(float* __restrict__ out) {
    extern __shared__ char smem[];
    uint32_t* s_pix  = (uint32_t*)smem;
    uint32_t* s_out4 = (uint32_t*)(smem + 512);
    const uint32_t sb = (uint32_t)__cvta_generic_to_shared(smem);

    const int t = threadIdx.x;
    const int w = t >> 5, lane = t & 31;
    const int g = lane >> 2, tig = lane & 3;
    const int ocHalf = w & 1, pxQ = w >> 1;          // 2 x 4 warp grid
    const int base = blockIdx.x * NT;

    if (t < NT) {
        int ng = base + t;
        int bb = ng / IMG, rr = ng - bb * IMG;
        int y = rr / HW, xx = rr - y * HW;
        s_pix[t] = (((uint32_t)bb * PADW + y) * PADW + xx) * CIN;
    }
    if (t < NT / 4) {
        int ng = base + t * 4;
        int bb = ng / IMG, rr = ng - bb * IMG;
        s_out4[t] = (uint32_t)bb * COUT * IMG + rr;
    }
    __syncthreads();

    float d[4][4][4];
    #pragma unroll
    for (int ao = 0; ao < 4; ao++)
        #pragma unroll
        for (int an = 0; an < 4; an++)
            #pragma unroll
            for (int j = 0; j < 4; j++) d[ao][an][j] = 0.f;

    // stage 32-channel chunk kk into buffer buf (0..2)
    auto stage = [&](int kk, int buf) {
        const uint32_t abuf = sb + SM_A0 + buf * 16384;
        const uint32_t bbuf = sb + SM_B0 + buf * 18432;
        const int k = kk >> 1, half = kk & 1;
        const float* asrc = g_wt2 + k * 8192 + half * 4096;
        #pragma unroll
        for (int it = 0; it < 4; it++) {
            int i = t + it * NTHR;                       // 1024 float4
            cp16(abuf + i * 16, asrc + i * 4);
        }
        const uint32_t shift = (uint32_t)((k / 3) * PADW + (k % 3)) * CIN + half * 32;
        #pragma unroll
        for (int it = 0; it < 4; it++) {
            int i = t + it * NTHR;                       // 1024 float4
            int px = i >> 3, c4 = i & 7;
            cp16(bbuf + (px * BSTR + c4 * 4) * 4,
                 g_xpad + s_pix[px] + shift + c4 * 4);
        }
    };

    stage(0, 0); CP_COMMIT();
    stage(1, 1); CP_COMMIT();

    int cur = 0;
    #pragma unroll 3
    for (int kk = 0; kk < 18; kk++) {
        if (kk < 17) { CP_WAIT(1); } else { CP_WAIT(0); }
        __syncthreads();

        const float* sA = (const float*)(smem + SM_A0 + cur * 16384);
        const float* sB = (const float*)(smem + SM_B0 + cur * 18432);
        const float* aBase = sA + ocHalf * 512 + lane * 4;
        const float* bBase = sB + (pxQ * 32 + g) * BSTR + tig;

        #pragma unroll
        for (int s = 0; s < 4; s++) {
            uint32_t a[4][4];
            #pragma unroll
            for (int ao = 0; ao < 4; ao++) {
                uint4 v = *(const uint4*)(aBase + s * 1024 + ao * 128);
                a[ao][0] = v.x; a[ao][1] = v.y; a[ao][2] = v.z; a[ao][3] = v.w;
            }
            uint32_t b0[4], b1[4];
            #pragma unroll
            for (int an = 0; an < 4; an++) {
                b0[an] = __float_as_uint(bBase[an * 8 * BSTR + s * 8]);
                b1[an] = __float_as_uint(bBase[an * 8 * BSTR + s * 8 + 4]);
            }
            #pragma unroll
            for (int ao = 0; ao < 4; ao++)
                #pragma unroll
                for (int an = 0; an < 4; an++)
                    mma8(d[ao][an], a[ao], b0[an], b1[an]);
        }

        // stage kk+2 into the buffer compute(kk-1) used; all warps are past
        // sync(kk) which follows their compute(kk-1) -> safe.
        if (kk < 16) {
            int nb = (cur == 0) ? 2 : cur - 1;   // (kk+2) % 3
            stage(kk + 2, nb);
            CP_COMMIT();
        }
        cur = (cur == 2) ? 0 : cur + 1;
    }

    // epilogue: accums -> sO[oc][132] -> coalesced STG.128
    __syncthreads();
    float* sO = (float*)(smem + SM_A0);
    #pragma unroll
    for (int ao = 0; ao < 4; ao++)
        #pragma unroll
        for (int an = 0; an < 4; an++)
            #pragma unroll
            for (int j = 0; j < 4; j++) {
                int oc = ocHalf * 64 + ao * 16 + g + ((j >> 1) << 3);
                int px = pxQ * 32 + an * 8 + 2 * tig + (j & 1);
                sO[oc * 132 + px] = d[ao][an][j];
            }
    __syncthreads();

    #pragma unroll
    for (int it = 0; it < 16; it++) {
        int i = t + it * NTHR;                           // 4096 float4
        int oc = i >> 5, q = i & 31;
        float4 v = *(const float4*)(sO + oc * 132 + q * 4);
        *(float4*)(out + (size_t)s_out4[q] + (size_t)oc * IMG) = v;
    }
}

extern "C" void kernel_launch(void* const* d_in, const int* in_sizes, int n_in,
                              void* d_out, int out_size) {
    const float* x = (const float*)d_in[0];
    const float* w = (const float*)d_in[1];
    float* out = (float*)d_out;

    k_prep<<<TGRID + (9 * COUT * CIN + NTHR - 1) / NTHR, NTHR>>>(x, w);

    cudaFuncSetAttribute(conv_mma, cudaFuncAttributeMaxDynamicSharedMemorySize, SM_TOT);
    conv_mma<<<NCTA, NTHR, SM_TOT>>>(out);
}

// round 9
// speedup vs baseline: 5.1360x; 1.5946x over previous
#include <cuda_runtime.h>
#include <cuda_fp16.h>
#include <cstdint>

// Conv2d 3x3 s1 p1: x[32,64,56,56] * w[128,64,3,3] -> out[32,128,56,56]
// FP16 implicit GEMM (fp32 accum), mma.sync m16n8k16. cp.async triple-buffered
// 64-channel k-chunks (9 taps, one barrier per step), 2 CTAs/SM.

#define B_    32
#define CIN   64
#define COUT  128
#define HW    56
#define PADW  58
#define IMG   (HW*HW)             // 3136
#define NPIX  (B_*IMG)            // 100352
#define NT    128                 // pixels per CTA
#define NCTA  (NPIX/NT)           // 784
#define BSTRH 72                  // B smem stride in halves (64 + 8 pad)
#define NTHR  256
#define TGRID (PADW*B_)           // 1856 transpose blocks

__device__ __half g_xpad[(size_t)B_*PADW*PADW*CIN];  // 13.8 MB, fp16 NHWC padded
__device__ __half g_wt2[9*COUT*CIN];                 // fragment-major fp16 weights

static __device__ __forceinline__ void mma16(float* d, const uint32_t* a,
                                             uint32_t b0, uint32_t b1) {
    asm volatile("mma.sync.aligned.m16n8k16.row.col.f32.f16.f16.f32 "
                 "{%0,%1,%2,%3}, {%4,%5,%6,%7}, {%8,%9}, {%0,%1,%2,%3};"
                 : "+f"(d[0]), "+f"(d[1]), "+f"(d[2]), "+f"(d[3])
                 : "r"(a[0]), "r"(a[1]), "r"(a[2]), "r"(a[3]), "r"(b0), "r"(b1));
}
static __device__ __forceinline__ void cp16(uint32_t saddr, const void* g) {
    asm volatile("cp.async.cg.shared.global [%0], [%1], 16;" :: "r"(saddr), "l"(g));
}
#define CP_COMMIT() asm volatile("cp.async.commit_group;" ::: "memory")
#define CP_WAIT(n)  asm volatile("cp.async.wait_group %0;" :: "n"(n) : "memory")

// ---------------- fused prep kernel ----------------
// blocks [0,1856): NCHW fp32 -> padded NHWC fp16 with border zeroing.
// blocks [1856..): weight reorder to m16n8k16 A-fragment-major fp16.
__global__ void k_prep(const float* __restrict__ x, const float* __restrict__ w) {
    const int bid = blockIdx.x, t = threadIdx.x;
    if (bid < TGRID) {
        int yp = bid % PADW, b = bid / PADW;
        __half* dst = g_xpad + ((size_t)b * PADW + yp) * PADW * CIN;
        if (yp == 0 || yp == PADW - 1) {
            for (int i = t; i < PADW * CIN; i += NTHR) dst[i] = __float2half(0.f);
            return;
        }
        __shared__ float s[CIN][HW + 1];
        int y = yp - 1;
        for (int i = t; i < CIN * HW; i += NTHR) {
            int c = i / HW, xx = i % HW;
            s[c][xx] = x[(((size_t)b * CIN + c) * HW + y) * HW + xx];
        }
        __syncthreads();
        if (t < 2 * CIN) {               // zero left/right halo columns
            int side = t >> 6, c = t & 63;
            dst[(side ? (PADW - 1) * CIN : 0) + c] = __float2half(0.f);
        }
        for (int i = t; i < HW * CIN; i += NTHR) {
            int px = i / CIN, c = i % CIN;
            dst[(px + 1) * CIN + c] = __float2half_rn(s[c][px]);
        }
    } else {
        // per kidx: [s(4)][atom(8)][lane(32)][j(8 halves)] = 8192 halves
        // oc = atom*16 + lane/4 + ((j>>1)&1)*8
        // c  = s*16 + 2*(lane&3) + (j&1) + ((j>>2)&1)*8
        int i = (bid - TGRID) * NTHR + t;
        if (i >= 9 * COUT * CIN) return;
        int kidx = i / 8192;
        int e    = i % 8192;
        int s    = e / 2048;
        int atom = (e / 256) & 7;
        int lane = (e >> 3) & 31;
        int j    = e & 7;
        int oc = atom * 16 + (lane >> 2) + ((j >> 1) & 1) * 8;
        int c  = s * 16 + 2 * (lane & 3) + (j & 1) + ((j >> 2) & 1) * 8;
        g_wt2[i] = __float2half_rn(w[((size_t)oc * CIN + c) * 9 + kidx]);
    }
}

// ---------------- main kernel ----------------
// smem/CTA: [0] s_pix(128 u32) [512] s_out4(32 u32)
//   [1024] A0,A1,A2 (16384 B each) [50176] B0,B1,B2 (18432 B each)
//   total 105472 -> 2 CTAs/SM. Epilogue reuses [1024..] as sO[128][132] f32.
#define SM_A0   1024
#define SM_B0   (SM_A0 + 3*16384)
#define SM_TOT  (SM_B0 + 3*NT*BSTRH*2)

__global__ __launch_bounds__(NTHR, 2) void conv_mma(float* __restrict__ out) {
    extern __shared__ char smem[];
    uint32_t* s_pix  = (uint32_t*)smem;
    uint32_t* s_out4 = (uint32_t*)(smem + 512);
    const uint32_t sb = (uint32_t)__cvta_generic_to_shared(smem);

    const int t = threadIdx.x;
    const int w = t >> 5, lane = t & 31;
    const int g = lane >> 2, tig = lane & 3;
    const int ocHalf = w & 1, pxQ = w >> 1;          // 2 x 4 warp grid
    const int base = blockIdx.x * NT;

    if (t < NT) {
        int ng = base + t;
        int bb = ng / IMG, rr = ng - bb * IMG;
        int y = rr / HW, xx = rr - y * HW;
        s_pix[t] = (((uint32_t)bb * PADW + y) * PADW + xx) * CIN;   // half units
    }
    if (t < NT / 4) {
        int ng = base + t * 4;
        int bb = ng / IMG, rr = ng - bb * IMG;
        s_out4[t] = (uint32_t)bb * COUT * IMG + rr;
    }
    __syncthreads();

    float d[4][4][4];
    #pragma unroll
    for (int ao = 0; ao < 4; ao++)
        #pragma unroll
        for (int an = 0; an < 4; an++)
            #pragma unroll
            for (int j = 0; j < 4; j++) d[ao][an][j] = 0.f;

    // stage 64-channel tap kidx into buffer buf (0..2)
    auto stage = [&](int kidx, int buf) {
        const uint32_t abuf = sb + SM_A0 + buf * 16384;
        const uint32_t bbuf = sb + SM_B0 + buf * 18432;
        const __half* asrc = g_wt2 + kidx * 8192;
        #pragma unroll
        for (int it = 0; it < 4; it++) {
            int i = t + it * NTHR;                       // 1024 x 16B
            cp16(abuf + i * 16, asrc + i * 8);
        }
        const uint32_t shift = (uint32_t)((kidx / 3) * PADW + (kidx % 3)) * CIN;
        #pragma unroll
        for (int it = 0; it < 4; it++) {
            int i = t + it * NTHR;                       // 1024 x 16B
            int px = i >> 3, c8 = i & 7;
            cp16(bbuf + px * (BSTRH * 2) + c8 * 16,
                 g_xpad + s_pix[px] + shift + c8 * 8);
        }
    };

    stage(0, 0); CP_COMMIT();
    stage(1, 1); CP_COMMIT();

    int cur = 0;
    #pragma unroll 3
    for (int kk = 0; kk < 9; kk++) {
        if (kk < 8) { CP_WAIT(1); } else { CP_WAIT(0); }
        __syncthreads();

        const char* sA  = smem + SM_A0 + cur * 16384;
        const char* sBc = smem + SM_B0 + cur * 18432;
        // A: offset = s*4096 + (ocHalf*4+ao)*512 + lane*16
        const char* aBase = sA + (ocHalf * 4) * 512 + lane * 16;
        // B: byte addr = px*144 + s*32 + tig*4, px = pxQ*32 + an*8 + g
        const char* bBase = sBc + (pxQ * 32 + g) * (BSTRH * 2) + tig * 4;

        #pragma unroll
        for (int s = 0; s < 4; s++) {
            uint32_t a[4][4];
            #pragma unroll
            for (int ao = 0; ao < 4; ao++) {
                uint4 v = *(const uint4*)(aBase + s * 4096 + ao * 512);
                a[ao][0] = v.x; a[ao][1] = v.y; a[ao][2] = v.z; a[ao][3] = v.w;
            }
            uint32_t b0[4], b1[4];
            #pragma unroll
            for (int an = 0; an < 4; an++) {
                b0[an] = *(const uint32_t*)(bBase + an * (8 * BSTRH * 2) + s * 32);
                b1[an] = *(const uint32_t*)(bBase + an * (8 * BSTRH * 2) + s * 32 + 16);
            }
            #pragma unroll
            for (int ao = 0; ao < 4; ao++)
                #pragma unroll
                for (int an = 0; an < 4; an++)
                    mma16(d[ao][an], a[ao], b0[an], b1[an]);
        }

        // stage kk+2 into the buffer compute(kk-1) used; all warps are past
        // sync(kk) which follows their compute(kk-1) -> safe.
        if (kk < 7) {
            int nb = (cur == 0) ? 2 : cur - 1;   // (kk+2) % 3
            stage(kk + 2, nb);
            CP_COMMIT();
        }
        cur = (cur == 2) ? 0 : cur + 1;
    }

    // epilogue: accums -> sO[oc][132] -> coalesced STG.128
    __syncthreads();
    float* sO = (float*)(smem + SM_A0);
    #pragma unroll
    for (int ao = 0; ao < 4; ao++)
        #pragma unroll
        for (int an = 0; an < 4; an++)
            #pragma unroll
            for (int j = 0; j < 4; j++) {
                int oc = ocHalf * 64 + ao * 16 + g + ((j >> 1) << 3);
                int px = pxQ * 32 + an * 8 + 2 * tig + (j & 1);
                sO[oc * 132 + px] = d[ao][an][j];
            }
    __syncthreads();

    #pragma unroll
    for (int it = 0; it < 16; it++) {
        int i = t + it * NTHR;                           // 4096 float4
        int oc = i >> 5, q = i & 31;
        float4 v = *(const float4*)(sO + oc * 132 + q * 4);
        *(float4*)(out + (size_t)s_out4[q] + (size_t)oc * IMG) = v;
    }
}

extern "C" void kernel_launch(void* const* d_in, const int* in_sizes, int n_in,
                              void* d_out, int out_size) {
    const float* x = (const float*)d_in[0];
    const float* w = (const float*)d_in[1];
    float* out = (float*)d_out;

    k_prep<<<TGRID + (9 * COUT * CIN + NTHR - 1) / NTHR, NTHR>>>(x, w);

    cudaFuncSetAttribute(conv_mma, cudaFuncAttributeMaxDynamicSharedMemorySize, SM_TOT);
    conv_mma<<<NCTA, NTHR, SM_TOT>>>(out);
}

// round 10
// speedup vs baseline: 5.4440x; 1.0600x over previous
#include <cuda_runtime.h>
#include <cuda_fp16.h>
#include <cstdint>

// Conv2d 3x3 s1 p1: x[32,64,56,56] * w[128,64,3,3] -> out[32,128,56,56]
// FP16 implicit GEMM (fp32 accum), mma.sync m16n8k16.
// 64x64 warp tile (4 warps, 128 thr), cp.async triple-buffered 64-ch taps,
// 2 CTAs/SM.

#define B_    32
#define CIN   64
#define COUT  128
#define HW    56
#define PADW  58
#define IMG   (HW*HW)             // 3136
#define NPIX  (B_*IMG)            // 100352
#define NT    128                 // pixels per CTA
#define NCTA  (NPIX/NT)           // 784
#define BSTRH 72                  // B smem stride in halves (64 + 8 pad)
#define NTHR  128
#define PTHR  256                 // prep threads
#define TGRID (PADW*B_)           // 1856 transpose blocks

__device__ __half g_xpad[(size_t)B_*PADW*PADW*CIN];  // 13.8 MB, fp16 NHWC padded
__device__ __half g_wt2[9*COUT*CIN];                 // fragment-major fp16 weights

static __device__ __forceinline__ void mma16(float* d, const uint32_t* a,
                                             uint32_t b0, uint32_t b1) {
    asm volatile("mma.sync.aligned.m16n8k16.row.col.f32.f16.f16.f32 "
                 "{%0,%1,%2,%3}, {%4,%5,%6,%7}, {%8,%9}, {%0,%1,%2,%3};"
                 : "+f"(d[0]), "+f"(d[1]), "+f"(d[2]), "+f"(d[3])
                 : "r"(a[0]), "r"(a[1]), "r"(a[2]), "r"(a[3]), "r"(b0), "r"(b1));
}
static __device__ __forceinline__ void cp16(uint32_t saddr, const void* g) {
    asm volatile("cp.async.cg.shared.global [%0], [%1], 16;" :: "r"(saddr), "l"(g));
}
#define CP_COMMIT() asm volatile("cp.async.commit_group;" ::: "memory")
#define CP_WAIT(n)  asm volatile("cp.async.wait_group %0;" :: "n"(n) : "memory")

// ---------------- fused prep kernel ----------------
__global__ void k_prep(const float* __restrict__ x, const float* __restrict__ w) {
    const int bid = blockIdx.x, t = threadIdx.x;
    if (bid < TGRID) {
        int yp = bid % PADW, b = bid / PADW;
        __half* dst = g_xpad + ((size_t)b * PADW + yp) * PADW * CIN;
        if (yp == 0 || yp == PADW - 1) {
            for (int i = t; i < PADW * CIN; i += PTHR) dst[i] = __float2half(0.f);
            return;
        }
        __shared__ float s[CIN][HW + 1];
        int y = yp - 1;
        for (int i = t; i < CIN * HW; i += PTHR) {
            int c = i / HW, xx = i % HW;
            s[c][xx] = x[(((size_t)b * CIN + c) * HW + y) * HW + xx];
        }
        __syncthreads();
        if (t < 2 * CIN) {               // zero left/right halo columns
            int side = t >> 6, c = t & 63;
            dst[(side ? (PADW - 1) * CIN : 0) + c] = __float2half(0.f);
        }
        for (int i = t; i < HW * CIN; i += PTHR) {
            int px = i / CIN, c = i % CIN;
            dst[(px + 1) * CIN + c] = __float2half_rn(s[c][px]);
        }
    } else {
        // per kidx: [s(4)][atom(8)][lane(32)][j(8 halves)] = 8192 halves
        int i = (bid - TGRID) * PTHR + t;
        if (i >= 9 * COUT * CIN) return;
        int kidx = i / 8192;
        int e    = i % 8192;
        int s    = e / 2048;
        int atom = (e / 256) & 7;
        int lane = (e >> 3) & 31;
        int j    = e & 7;
        int oc = atom * 16 + (lane >> 2) + ((j >> 1) & 1) * 8;
        int c  = s * 16 + 2 * (lane & 3) + (j & 1) + ((j >> 2) & 1) * 8;
        g_wt2[i] = __float2half_rn(w[((size_t)oc * CIN + c) * 9 + kidx]);
    }
}

// ---------------- main kernel ----------------
// smem/CTA: [0] s_pix(128 u32) [512] s_out4(32 u32)
//   [1024] A0,A1,A2 (16384 B each) [50176] B0,B1,B2 (18432 B each)
//   total 105472 -> 2 CTAs/SM. Epilogue reuses [1024..] as sO[128][132] f32.
#define SM_A0   1024
#define SM_B0   (SM_A0 + 3*16384)
#define SM_TOT  (SM_B0 + 3*NT*BSTRH*2)

__global__ __launch_bounds__(NTHR, 2) void conv_mma(float* __restrict__ out) {
    extern __shared__ char smem[];
    uint32_t* s_pix  = (uint32_t*)smem;
    uint32_t* s_out4 = (uint32_t*)(smem + 512);
    const uint32_t sb = (uint32_t)__cvta_generic_to_shared(smem);

    const int t = threadIdx.x;
    const int w = t >> 5, lane = t & 31;
    const int g = lane >> 2, tig = lane & 3;
    const int ocHalf = w & 1, pxHalf = w >> 1;       // 2 x 2 warp grid, 64x64 tile
    const int base = blockIdx.x * NT;

    {
        int ng = base + t;
        int bb = ng / IMG, rr = ng - bb * IMG;
        int y = rr / HW, xx = rr - y * HW;
        s_pix[t] = (((uint32_t)bb * PADW + y) * PADW + xx) * CIN;   // half units
    }
    if (t < NT / 4) {
        int ng = base + t * 4;
        int bb = ng / IMG, rr = ng - bb * IMG;
        s_out4[t] = (uint32_t)bb * COUT * IMG + rr;
    }
    __syncthreads();

    float d[4][8][4];                                 // [ao][an][j] = 128 regs
    #pragma unroll
    for (int ao = 0; ao < 4; ao++)
        #pragma unroll
        for (int an = 0; an < 8; an++)
            #pragma unroll
            for (int j = 0; j < 4; j++) d[ao][an][j] = 0.f;

    // stage 64-channel tap kidx into buffer buf (0..2)
    auto stage = [&](int kidx, int buf) {
        const uint32_t abuf = sb + SM_A0 + buf * 16384;
        const uint32_t bbuf = sb + SM_B0 + buf * 18432;
        const __half* asrc = g_wt2 + kidx * 8192;
        #pragma unroll
        for (int it = 0; it < 8; it++) {
            int i = t + it * NTHR;                       // 1024 x 16B
            cp16(abuf + i * 16, asrc + i * 8);
        }
        const uint32_t shift = (uint32_t)((kidx / 3) * PADW + (kidx % 3)) * CIN;
        #pragma unroll
        for (int it = 0; it < 8; it++) {
            int i = t + it * NTHR;                       // 1024 x 16B
            int px = i >> 3, c8 = i & 7;
            cp16(bbuf + px * (BSTRH * 2) + c8 * 16,
                 g_xpad + s_pix[px] + shift + c8 * 8);
        }
    };

    stage(0, 0); CP_COMMIT();
    stage(1, 1); CP_COMMIT();

    int cur = 0;
    #pragma unroll 3
    for (int kk = 0; kk < 9; kk++) {
        if (kk < 8) { CP_WAIT(1); } else { CP_WAIT(0); }
        __syncthreads();

        const char* sA  = smem + SM_A0 + cur * 16384;
        const char* sBc = smem + SM_B0 + cur * 18432;
        // A: offset = s*4096 + (ocHalf*4+ao)*512 + lane*16
        const char* aBase = sA + (ocHalf * 4) * 512 + lane * 16;
        // B: byte addr = px*144 + tig*4 + s*32, px = pxHalf*64 + an*8 + g
        const char* bBase = sBc + (pxHalf * 64 + g) * (BSTRH * 2) + tig * 4;

        #pragma unroll
        for (int s = 0; s < 4; s++) {
            uint32_t a[4][4];
            #pragma unroll
            for (int ao = 0; ao < 4; ao++) {
                uint4 v = *(const uint4*)(aBase + s * 4096 + ao * 512);
                a[ao][0] = v.x; a[ao][1] = v.y; a[ao][2] = v.z; a[ao][3] = v.w;
            }
            uint32_t b0[8], b1[8];
            #pragma unroll
            for (int an = 0; an < 8; an++) {
                b0[an] = *(const uint32_t*)(bBase + an * (8 * BSTRH * 2) + s * 32);
                b1[an] = *(const uint32_t*)(bBase + an * (8 * BSTRH * 2) + s * 32 + 16);
            }
            #pragma unroll
            for (int ao = 0; ao < 4; ao++)
                #pragma unroll
                for (int an = 0; an < 8; an++)
                    mma16(d[ao][an], a[ao], b0[an], b1[an]);
        }

        if (kk < 7) {
            int nb = (cur == 0) ? 2 : cur - 1;   // (kk+2) % 3
            stage(kk + 2, nb);
            CP_COMMIT();
        }
        cur = (cur == 2) ? 0 : cur + 1;
    }

    // epilogue: accums -> sO[oc][132] -> coalesced STG.128
    __syncthreads();
    float* sO = (float*)(smem + SM_A0);
    #pragma unroll
    for (int ao = 0; ao < 4; ao++)
        #pragma unroll
        for (int an = 0; an < 8; an++)
            #pragma unroll
            for (int j = 0; j < 4; j++) {
                int oc = ocHalf * 64 + ao * 16 + g + ((j >> 1) << 3);
                int px = pxHalf * 64 + an * 8 + 2 * tig + (j & 1);
                sO[oc * 132 + px] = d[ao][an][j];
            }
    __syncthreads();

    #pragma unroll
    for (int it = 0; it < 32; it++) {
        int i = t + it * NTHR;                           // 4096 float4
        int oc = i >> 5, q = i & 31;
        float4 v = *(const float4*)(sO + oc * 132 + q * 4);
        *(float4*)(out + (size_t)s_out4[q] + (size_t)oc * IMG) = v;
    }
}

extern "C" void kernel_launch(void* const* d_in, const int* in_sizes, int n_in,
                              void* d_out, int out_size) {
    const float* x = (const float*)d_in[0];
    const float* w = (const float*)d_in[1];
    float* out = (float*)d_out;

    k_prep<<<TGRID + (9 * COUT * CIN + PTHR - 1) / PTHR, PTHR>>>(x, w);

    cudaFuncSetAttribute(conv_mma, cudaFuncAttributeMaxDynamicSharedMemorySize, SM_TOT);
    conv_mma<<<NCTA, NTHR, SM_TOT>>>(out);
}

// round 12
// speedup vs baseline: 5.6124x; 1.0309x over previous
#include <cuda_runtime.h>
#include <cuda_fp16.h>
#include <cstdint>

// Conv2d 3x3 s1 p1: x[32,64,56,56] * w[128,64,3,3] -> out[32,128,56,56]
// FP16 implicit GEMM (fp32 accum), mma.sync m16n8k16. 64x64 warp tile
// (4 warps). B pixel-halo staged ONCE per CTA (368 slots — covers the
// 119-pad-row jump at batch-crossing tiles); A taps cp.async triple-buffered.
// 2 CTAs/SM.

#define B_    32
#define CIN   64
#define COUT  128
#define HW    56
#define PADW  58
#define IMG   (HW*HW)             // 3136
#define NPIX  (B_*IMG)            // 100352
#define NT    128                 // pixels per CTA
#define NCTA  (NPIX/NT)           // 784
#define BSTRB 144                 // bytes per halo slot row (72 halves)
#define NSLOT 368                 // staged halo slot rows (max read slot = 367)
#define NTHR  128
#define PTHR  256                 // prep threads
#define TGRID (PADW*B_)           // 1856 transpose blocks

__device__ __half g_xpad[(size_t)B_*PADW*PADW*CIN];  // 13.8 MB, fp16 NHWC padded
__device__ __half g_wt2[9*COUT*CIN];                 // fragment-major fp16 weights

#define XPAD_HALVES ((size_t)B_*PADW*PADW*CIN)

static __device__ __forceinline__ void mma16(float* d, const uint32_t* a,
                                             uint32_t b0, uint32_t b1) {
    asm volatile("mma.sync.aligned.m16n8k16.row.col.f32.f16.f16.f32 "
                 "{%0,%1,%2,%3}, {%4,%5,%6,%7}, {%8,%9}, {%0,%1,%2,%3};"
                 : "+f"(d[0]), "+f"(d[1]), "+f"(d[2]), "+f"(d[3])
                 : "r"(a[0]), "r"(a[1]), "r"(a[2]), "r"(a[3]), "r"(b0), "r"(b1));
}
static __device__ __forceinline__ void cp16(uint32_t saddr, const void* g) {
    asm volatile("cp.async.cg.shared.global [%0], [%1], 16;" :: "r"(saddr), "l"(g));
}
#define CP_COMMIT() asm volatile("cp.async.commit_group;" ::: "memory")
#define CP_WAIT(n)  asm volatile("cp.async.wait_group %0;" :: "n"(n) : "memory")

// ---------------- fused prep kernel (unchanged) ----------------
__global__ void k_prep(const float* __restrict__ x, const float* __restrict__ w) {
    const int bid = blockIdx.x, t = threadIdx.x;
    if (bid < TGRID) {
        int yp = bid % PADW, b = bid / PADW;
        __half* dst = g_xpad + ((size_t)b * PADW + yp) * PADW * CIN;
        if (yp == 0 || yp == PADW - 1) {
            for (int i = t; i < PADW * CIN; i += PTHR) dst[i] = __float2half(0.f);
            return;
        }
        __shared__ float s[CIN][HW + 1];
        int y = yp - 1;
        for (int i = t; i < CIN * HW; i += PTHR) {
            int c = i / HW, xx = i % HW;
            s[c][xx] = x[(((size_t)b * CIN + c) * HW + y) * HW + xx];
        }
        __syncthreads();
        if (t < 2 * CIN) {               // zero left/right halo columns
            int side = t >> 6, c = t & 63;
            dst[(side ? (PADW - 1) * CIN : 0) + c] = __float2half(0.f);
        }
        for (int i = t; i < HW * CIN; i += PTHR) {
            int px = i / CIN, c = i % CIN;
            dst[(px + 1) * CIN + c] = __float2half_rn(s[c][px]);
        }
    } else {
        // per kidx: [s(4)][atom(8)][lane(32)][j(8 halves)] = 8192 halves
        int i = (bid - TGRID) * PTHR + t;
        if (i >= 9 * COUT * CIN) return;
        int kidx = i / 8192;
        int e    = i % 8192;
        int s    = e / 2048;
        int atom = (e / 256) & 7;
        int lane = (e >> 3) & 31;
        int j    = e & 7;
        int oc = atom * 16 + (lane >> 2) + ((j >> 1) & 1) * 8;
        int c  = s * 16 + 2 * (lane & 3) + (j & 1) + ((j >> 2) & 1) * 8;
        g_wt2[i] = __float2half_rn(w[((size_t)oc * CIN + c) * 9 + kidx]);
    }
}

// ---------------- main kernel ----------------
// smem/CTA: [0] s_out4(32 u32)  [1024] A0,A1,A2 (16384 B each)
//           [50176] halo (368 slots x 144 B = 52992)   total 103168
//   -> 2 CTAs/SM. Epilogue reuses [1024..] as sO[128][132] f32 (67584 B).
#define SM_A0   1024
#define SM_HALO (SM_A0 + 3*16384)
#define SM_TOT  (SM_HALO + NSLOT*BSTRB)

__global__ __launch_bounds__(NTHR, 2) void conv_mma(float* __restrict__ out) {
    extern __shared__ char smem[];
    uint32_t* s_out4 = (uint32_t*)smem;
    const uint32_t sb = (uint32_t)__cvta_generic_to_shared(smem);

    const int t = threadIdx.x;
    const int w = t >> 5, lane = t & 31;
    const int g = lane >> 2, tig = lane & 3;
    const int ocHalf = w & 1, pxHalf = w >> 1;       // 2 x 2 warp grid, 64x64 tile
    const int base = blockIdx.x * NT;

    // pad-address of the tile's first pixel (halves) — reference for slots
    size_t pix0;
    {
        int bb = base / IMG, rr = base - bb * IMG;
        int y = rr / HW, xx = rr - y * HW;
        pix0 = (((size_t)bb * PADW + y) * PADW + xx) * CIN;
    }

    // per-thread B slot byte-offsets for the 8 'an' sub-tiles
    uint32_t bOff[8];
    #pragma unroll
    for (int an = 0; an < 8; an++) {
        int pg = base + pxHalf * 64 + an * 8 + g;        // global pixel id
        int bb = pg / IMG, rr = pg - bb * IMG;
        int y = rr / HW, xx = rr - y * HW;
        size_t pa = (((size_t)bb * PADW + y) * PADW + xx) * CIN;
        uint32_t slot = (uint32_t)((pa - pix0) >> 6);    // /CIN, max 249
        bOff[an] = SM_HALO + slot * BSTRB + tig * 4;
    }
    if (t < NT / 4) {
        int ng = base + t * 4;
        int bb = ng / IMG, rr = ng - bb * IMG;
        s_out4[t] = (uint32_t)bb * COUT * IMG + rr;
    }

    float d[4][8][4];                                 // [ao][an][j] = 128 regs
    #pragma unroll
    for (int ao = 0; ao < 4; ao++)
        #pragma unroll
        for (int an = 0; an < 8; an++)
            #pragma unroll
            for (int j = 0; j < 4; j++) d[ao][an][j] = 0.f;

    // stage A tap kidx into buffer buf (0..2)
    auto stageA = [&](int kidx, int buf) {
        const uint32_t abuf = sb + SM_A0 + buf * 16384;
        const __half* asrc = g_wt2 + kidx * 8192;
        #pragma unroll
        for (int it = 0; it < 8; it++) {
            int i = t + it * NTHR;                       // 1024 x 16B
            cp16(abuf + i * 16, asrc + i * 8);
        }
    };

    // stage the 368-slot B halo once (clamped at array end; clamped slots
    // are only ever read as dead taps of nonexistent pixels)
    {
        #pragma unroll
        for (int it = 0; it < 23; it++) {
            int i = t + it * NTHR;                       // 2944 x 16B
            int slot = i >> 3, c8 = i & 7;
            size_t off = pix0 + (size_t)slot * CIN + c8 * 8;
            if (off > XPAD_HALVES - 8) off = XPAD_HALVES - 8;
            cp16(sb + SM_HALO + slot * BSTRB + c8 * 16, g_xpad + off);
        }
    }
    stageA(0, 0); CP_COMMIT();        // group0 = halo + A0
    stageA(1, 1); CP_COMMIT();        // group1 = A1

    int cur = 0;
    #pragma unroll 3
    for (int kk = 0; kk < 9; kk++) {
        if (kk < 8) { CP_WAIT(1); } else { CP_WAIT(0); }
        __syncthreads();

        const char* sA = smem + SM_A0 + cur * 16384;
        const char* aBase = sA + (ocHalf * 4) * 512 + lane * 16;
        const uint32_t tapB = (uint32_t)((kk / 3) * PADW + (kk % 3)) * BSTRB;

        #pragma unroll
        for (int s = 0; s < 4; s++) {
            uint32_t a[4][4];
            #pragma unroll
            for (int ao = 0; ao < 4; ao++) {
                uint4 v = *(const uint4*)(aBase + s * 4096 + ao * 512);
                a[ao][0] = v.x; a[ao][1] = v.y; a[ao][2] = v.z; a[ao][3] = v.w;
            }
            uint32_t b0[8], b1[8];
            #pragma unroll
            for (int an = 0; an < 8; an++) {
                const char* bp = smem + bOff[an] + tapB + s * 32;
                b0[an] = *(const uint32_t*)(bp);
                b1[an] = *(const uint32_t*)(bp + 16);
            }
            #pragma unroll
            for (int ao = 0; ao < 4; ao++)
                #pragma unroll
                for (int an = 0; an < 8; an++)
                    mma16(d[ao][an], a[ao], b0[an], b1[an]);
        }

        // stage A(kk+2) into the buffer compute(kk-1) used; all warps are past
        // sync(kk) which follows their compute(kk-1) -> safe.
        if (kk < 7) {
            int nb = (cur == 0) ? 2 : cur - 1;   // (kk+2) % 3
            stageA(kk + 2, nb);
            CP_COMMIT();
        }
        cur = (cur == 2) ? 0 : cur + 1;
    }

    // epilogue: accums -> sO[oc][132] -> coalesced STG.128
    __syncthreads();
    float* sO = (float*)(smem + SM_A0);
    #pragma unroll
    for (int ao = 0; ao < 4; ao++)
        #pragma unroll
        for (int an = 0; an < 8; an++)
            #pragma unroll
            for (int j = 0; j < 4; j++) {
                int oc = ocHalf * 64 + ao * 16 + g + ((j >> 1) << 3);
                int px = pxHalf * 64 + an * 8 + 2 * tig + (j & 1);
                sO[oc * 132 + px] = d[ao][an][j];
            }
    __syncthreads();

    #pragma unroll
    for (int it = 0; it < 32; it++) {
        int i = t + it * NTHR;                           // 4096 float4
        int oc = i >> 5, q = i & 31;
        float4 v = *(const float4*)(sO + oc * 132 + q * 4);
        *(float4*)(out + (size_t)s_out4[q] + (size_t)oc * IMG) = v;
    }
}

extern "C" void kernel_launch(void* const* d_in, const int* in_sizes, int n_in,
                              void* d_out, int out_size) {
    const float* x = (const float*)d_in[0];
    const float* w = (const float*)d_in[1];
    float* out = (float*)d_out;

    k_prep<<<TGRID + (9 * COUT * CIN + PTHR - 1) / PTHR, PTHR>>>(x, w);

    cudaFuncSetAttribute(conv_mma, cudaFuncAttributeMaxDynamicSharedMemorySize, SM_TOT);
    conv_mma<<<NCTA, NTHR, SM_TOT>>>(out);
}